// round 17
// baseline (speedup 1.0000x reference)
#include <cuda_runtime.h>

#define BATCH 32
#define SEQ   512
#define HID   512
#define G4    2048
#define NCTA  128
#define TPB   512
#define HSTR2 128
#define PBC   10

typedef unsigned long long u64;

// ---------------- static device scratch ----------------
__device__ float g_zx0[(size_t)BATCH * SEQ * G4];
__device__ float g_wstage[2][(size_t)NCTA * 8192];   // Wk1, Wr1 in staged layout (8MB)
__device__ float g_h0[2][BATCH * HID];
__device__ float g_h1[2][BATCH * HID];
__device__ unsigned g_cnt0;

// ---------------- packed f32x2 helpers ----------------
__device__ __forceinline__ u64 pk(float lo, float hi) {
    u64 r; asm("mov.b64 %0, {%1,%2};" : "=l"(r) : "f"(lo), "f"(hi)); return r;
}
__device__ __forceinline__ float2 upk(u64 v) {
    float2 r; asm("mov.b64 {%0,%1}, %2;" : "=f"(r.x), "=f"(r.y) : "l"(v)); return r;
}
__device__ __forceinline__ void fma2(u64 &acc, u64 a, u64 b) {
    asm("fma.rn.f32x2 %0, %1, %2, %0;" : "+l"(acc) : "l"(a), "l"(b));
}
__device__ __forceinline__ u64 add2(u64 a, u64 b) {
    u64 r; asm("add.rn.f32x2 %0, %1, %2;" : "=l"(r) : "l"(a), "l"(b)); return r;
}
__device__ __forceinline__ void arrive_release(unsigned* p) {
    asm volatile("red.release.gpu.global.add.u32 [%0], 1;" :: "l"(p) : "memory");
}
__device__ __forceinline__ unsigned ld_acquire_u(const unsigned* p) {
    unsigned v;
    asm volatile("ld.acquire.gpu.u32 %0, [%1];" : "=r"(v) : "l"(p) : "memory");
    return v;
}
__device__ __forceinline__ float sigf(float x)  { return 1.f / (1.f + __expf(-x)); }
__device__ __forceinline__ float tanhfa(float x){ return 2.f / (1.f + __expf(-2.f * x)) - 1.f; }

// ---------------- init ----------------
__global__ void init_kernel() {
    int i = blockIdx.x * blockDim.x + threadIdx.x;
    if (i == 0) g_cnt0 = 0u;
    if (i < BATCH * HID) {
        g_h0[0][i] = 0.f; g_h0[1][i] = 0.f;
        g_h1[0][i] = 0.f; g_h1[1][i] = 0.f;
    }
}

// ---------------- embedding gather ----------------
__global__ void embed_kernel(const int* __restrict__ src,
                             const float* __restrict__ emb,
                             float* __restrict__ oe) {
    int bs = blockIdx.x;
    int tok = src[bs];
    const float4* er = (const float4*)(emb + (size_t)tok * HID);
    float4* orow = (float4*)(oe + (size_t)bs * HID);
    orow[threadIdx.x] = er[threadIdx.x];
}

// ---------------- pre-transpose Wk1/Wr1 into staged layout ----------------
__global__ __launch_bounds__(256) void wstage_kernel(const float* __restrict__ Wk,
                                                     const float* __restrict__ Wr) {
    const int cid = blockIdx.x;
    const int tid = threadIdx.x;
    const int u0 = cid * 4;
    const float* srcs[2] = { Wk + (size_t)HID * G4, Wr + (size_t)HID * G4 };
#pragma unroll
    for (int m = 0; m < 2; m++) {
        const float* srcm = srcs[m];
        float* dst = &g_wstage[m][(size_t)cid * 8192];
        for (int i = 0; i < 8; i++) {
            int t2 = tid + 256 * i;            // 2048: k(512) x g(4)
            int g = t2 & 3, k = t2 >> 2;
            float4 v = *(const float4*)(srcm + (size_t)k * G4 + g * HID + u0);
            int ch = k >> 2, kk = k & 3;
            float* d = dst + ch * 64 + g * 16 + kk;
            d[0]  = v.x; d[4]  = v.y; d[8]  = v.z; d[12] = v.w;
        }
    }
}

// ---------------- precompute GEMM: Zx0 = X @ Wk0 + b0 ----------------
__global__ __launch_bounds__(256) void gemm_zx0(const float* __restrict__ X,
                                                const float* __restrict__ Wk,
                                                const float* __restrict__ bias) {
    __shared__ float As[16][128];
    __shared__ float Bs[16][128];
    const int bm = blockIdx.y * 128;
    const int bn = blockIdx.x * 128;
    const int tid = threadIdx.x;
    const int tx = tid & 15, ty = tid >> 4;

    u64 acc[4][8];
#pragma unroll
    for (int p = 0; p < 4; p++)
#pragma unroll
        for (int q = 0; q < 8; q++) acc[p][q] = 0ull;

    for (int k0 = 0; k0 < 512; k0 += 16) {
#pragma unroll
        for (int r = 0; r < 2; r++) {
            int i = tid + 256 * r;
            int m = i >> 2, kq = (i & 3) * 4;
            float4 v = *(const float4*)(X + (size_t)(bm + m) * 512 + k0 + kq);
            As[kq + 0][m] = v.x; As[kq + 1][m] = v.y;
            As[kq + 2][m] = v.z; As[kq + 3][m] = v.w;
        }
#pragma unroll
        for (int r = 0; r < 2; r++) {
            int i = tid + 256 * r;
            int k = i >> 5, n4 = (i & 31) * 4;
            *(float4*)&Bs[k][n4] = *(const float4*)(Wk + (size_t)(k0 + k) * G4 + bn + n4);
        }
        __syncthreads();
#pragma unroll
        for (int kk = 0; kk < 16; kk++) {
            u64 a0 = *(const u64*)&As[kk][ty * 8 + 0];
            u64 a1 = *(const u64*)&As[kk][ty * 8 + 2];
            u64 a2 = *(const u64*)&As[kk][ty * 8 + 4];
            u64 a3 = *(const u64*)&As[kk][ty * 8 + 6];
            float4 b0 = *(const float4*)&Bs[kk][tx * 8];
            float4 b1 = *(const float4*)&Bs[kk][tx * 8 + 4];
            u64 bb[8];
            bb[0] = pk(b0.x, b0.x); bb[1] = pk(b0.y, b0.y);
            bb[2] = pk(b0.z, b0.z); bb[3] = pk(b0.w, b0.w);
            bb[4] = pk(b1.x, b1.x); bb[5] = pk(b1.y, b1.y);
            bb[6] = pk(b1.z, b1.z); bb[7] = pk(b1.w, b1.w);
#pragma unroll
            for (int q = 0; q < 8; q++) {
                fma2(acc[0][q], a0, bb[q]);
                fma2(acc[1][q], a1, bb[q]);
                fma2(acc[2][q], a2, bb[q]);
                fma2(acc[3][q], a3, bb[q]);
            }
        }
        __syncthreads();
    }
#pragma unroll
    for (int p = 0; p < 4; p++) {
#pragma unroll
        for (int q = 0; q < 8; q++) {
            int m0 = bm + ty * 8 + 2 * p;
            int n = bn + tx * 8 + q;
            float bb = bias[n];
            float2 v = upk(acc[p][q]);
            g_zx0[(size_t)m0 * G4 + n]       = v.x + bb;
            g_zx0[(size_t)(m0 + 1) * G4 + n] = v.y + bb;
        }
    }
}

// ================= persistent recurrence: 3 phases, double-buffered hs =================
// smem (floats): ws0 8192 | hs0 @8192 (16384) | hs1 @24576 (16384) |
//                part0 @40960 (5120) | part1 @46080 (5120)  => 51200 fl = 204,800 B
#define WS0_OFF  0
#define HS0_OFF  8192
#define HS1_OFF  24576
#define P0_OFF   40960
#define P1_OFF   46080
#define SMEM_FL  51200

// fused: A (smem w) + B (global w), shared h loads
__device__ __forceinline__ void accumAB2(u64* accA, u64* accB, const float* hs,
                                         const float* ws, const float* __restrict__ gw,
                                         int kseg, int c2, int bbase) {
    const int ch0 = kseg * 16;
    const float* wp0 = ws + ch0 * 64 + c2 * 4;
    const float* wp1 = gw + ch0 * 64 + c2 * 4;
    const float* hp  = hs + ch0 * HSTR2;
#pragma unroll 8
    for (int t = 0; t < 16; t++) {
        ulonglong2 wa1 = __ldg((const ulonglong2*)(wp1 + t * 64));
        ulonglong2 wb1 = __ldg((const ulonglong2*)(wp1 + t * 64 + 32));
        ulonglong2 wa0 = *(const ulonglong2*)(wp0 + t * 64);
        ulonglong2 wb0 = *(const ulonglong2*)(wp0 + t * 64 + 32);
#pragma unroll
        for (int bi = 0; bi < 4; bi++) {
            const int b = bbase + bi * 4;
            ulonglong2 h = *(const ulonglong2*)(hp + t * HSTR2 + b * 4);
            fma2(accA[bi],     wa0.x, h.x); fma2(accA[bi],     wa0.y, h.y);
            fma2(accA[4 + bi], wb0.x, h.x); fma2(accA[4 + bi], wb0.y, h.y);
            fma2(accB[bi],     wa1.x, h.x); fma2(accB[bi],     wa1.y, h.y);
            fma2(accB[4 + bi], wb1.x, h.x); fma2(accB[4 + bi], wb1.y, h.y);
        }
    }
}

// C: global w, smem h
__device__ __forceinline__ void accumC_g(u64* acc, const float* hs,
                                         const float* __restrict__ gw,
                                         int kseg, int c2, int bbase) {
    const int ch0 = kseg * 16;
    const float* wp = gw + ch0 * 64 + c2 * 4;
    const float* hp = hs + ch0 * HSTR2;
#pragma unroll 8
    for (int t = 0; t < 16; t++) {
        ulonglong2 wa = __ldg((const ulonglong2*)(wp + t * 64));
        ulonglong2 wb = __ldg((const ulonglong2*)(wp + t * 64 + 32));
#pragma unroll
        for (int bi = 0; bi < 4; bi++) {
            const int b = bbase + bi * 4;
            ulonglong2 h = *(const ulonglong2*)(hp + t * HSTR2 + b * 4);
            fma2(acc[bi],     wa.x, h.x); fma2(acc[bi],     wa.y, h.y);
            fma2(acc[4 + bi], wb.x, h.x); fma2(acc[4 + bi], wb.y, h.y);
        }
    }
}

// partials: part[cell * PBC + kseg], cell = b*16 + ci
__device__ __forceinline__ void dumpPf(float* part, const u64* acc,
                                       int kseg, int c2, int bbase) {
#pragma unroll
    for (int cc = 0; cc < 2; cc++)
#pragma unroll
        for (int bi = 0; bi < 4; bi++) {
            float2 v = upk(acc[cc * 4 + bi]);
            part[((bbase + bi * 4) * 16 + (c2 + 8 * cc)) * PBC + kseg] = v.x + v.y;
        }
}

__device__ __forceinline__ float redcellf(const float* part, int cell) {
    const float* p = part + cell * PBC;
    u64 s0 = add2(*(const u64*)(p + 0), *(const u64*)(p + 2));
    u64 s1 = add2(*(const u64*)(p + 4), *(const u64*)(p + 6));
    float2 v = upk(add2(s0, s1));
    return v.x + v.y;
}

// stage one h buffer (preloop / Phase III)
__device__ __forceinline__ void stage2(float* hs, const float* __restrict__ src, int tid) {
    const int cidx = tid & 127;
    const int brow = tid >> 7;
#pragma unroll
    for (int i = 0; i < 8; i++) {
        const int b = brow * 8 + i;
        float4 v = __ldcg((const float4*)(src + b * HID + cidx * 4));
        *(float4*)(hs + cidx * HSTR2 + b * 4) = v;
    }
}

__global__ __launch_bounds__(TPB, 1) void persist_kernel(const float* __restrict__ Wk,
                                                         const float* __restrict__ Wr,
                                                         const float* __restrict__ bias,
                                                         float* __restrict__ out) {
    extern __shared__ float smf[];
    float* ws0 = smf + WS0_OFF;
    float* hs0 = smf + HS0_OFF;
    float* hs1 = smf + HS1_OFF;
    float* part0 = smf + P0_OFF;
    float* part1 = smf + P1_OFF;

    const int tid = threadIdx.x;
    const int cid = blockIdx.x;
    const int u0 = cid * 4;
    const int lane = tid & 31;
    const int kseg = (tid >> 5) >> 1;
    const int bhalf = (tid >> 5) & 1;
    const int c2 = lane & 7;
    const int bg = lane >> 3;
    const int bbase = bhalf * 16 + bg;
    const int cidx = tid & 127;
    const int brow = tid >> 7;

    const float* gWk1 = &g_wstage[0][(size_t)cid * 8192];
    const float* gWr1 = &g_wstage[1][(size_t)cid * 8192];

    // ---- stage layer0 Wr into smem once ----
    {
        for (int i = 0; i < 4; i++) {
            int t2 = tid + TPB * i;
            int g = t2 & 3, k = t2 >> 2;
            float4 v = __ldcg((const float4*)(Wr + (size_t)k * G4 + g * HID + u0));
            int ch = k >> 2, kk = k & 3;
            float* d = ws0 + ch * 64 + g * 16 + kk;
            d[0]  = v.x; d[4]  = v.y; d[8]  = v.z; d[12] = v.w;
        }
    }

    // cell mapping: thread tid -> cell tid (b = tid>>4, ci = tid&15)
    const int rb = tid >> 4, rci = tid & 15;
    const int rcol = (rci >> 2) * HID + u0 + (rci & 3);
    const float biasB = bias[G4 + rcol];

    const int ul = lane & 3;
    const bool isGate = (lane & 15) < 4;
    const int shbase = lane & 16;
    float c0reg = 0.f, c1reg = 0.f;

    // pre-loop: stage both h buffers (zeros)
    stage2(hs0, g_h0[0], tid);
    stage2(hs1, g_h1[0], tid);
    __syncthreads();

    for (int j = 0; j <= SEQ; j++) {
        const int wb2 = (j + 1) & 1;

        // ---- Phase I: all three GEMMs; dump both partial sets ----
        float zx = 0.f;
        if (j < SEQ)
            zx = __ldcg(&g_zx0[((size_t)(rb * SEQ + j)) * G4 + rcol]);
        u64 accA[8], accB[8];
#pragma unroll
        for (int q = 0; q < 8; q++) { accA[q] = 0ull; accB[q] = 0ull; }
        accumAB2(accA, accB, hs0, ws0, gWk1, kseg, c2, bbase);   // A=Wr0.h0, B=Wk1.h0
        accumC_g(accB, hs1, gWr1, kseg, c2, bbase);              // += Wr1.h1
        dumpPf(part0, accA, kseg, c2, bbase);
        dumpPf(part1, accB, kseg, c2, bbase);
        __syncthreads();

        // ---- Phase II: both reduces + both gate blocks ----
        if (j < SEQ) {
            float z = redcellf(part0, tid) + zx;
            float zi = __shfl_sync(0xffffffffu, z, shbase | ul);
            float zf = __shfl_sync(0xffffffffu, z, shbase | (ul + 4));
            float zg = __shfl_sync(0xffffffffu, z, shbase | (ul + 8));
            float zo = __shfl_sync(0xffffffffu, z, shbase | (ul + 12));
            if (isGate) {
                float ig = sigf(zi), fg = sigf(zf), gg = tanhfa(zg), og = sigf(zo);
                c0reg = fg * c0reg + ig * gg;
                float hn = og * tanhfa(c0reg);
                g_h0[wb2][rb * HID + u0 + ul] = hn;
            }
        }
        {
            float z = redcellf(part1, tid) + biasB;
            float zi = __shfl_sync(0xffffffffu, z, shbase | ul);
            float zf = __shfl_sync(0xffffffffu, z, shbase | (ul + 4));
            float zg = __shfl_sync(0xffffffffu, z, shbase | (ul + 8));
            float zo = __shfl_sync(0xffffffffu, z, shbase | (ul + 12));
            if (isGate && j >= 1) {
                float ig = sigf(zi), fg = sigf(zf), gg = tanhfa(zg), og = sigf(zo);
                c1reg = fg * c1reg + ig * gg;
                float hn = og * tanhfa(c1reg);
                g_h1[wb2][rb * HID + u0 + ul] = hn;
                out[(size_t)rb * SEQ * HID + (size_t)(j - 1) * HID + u0 + ul] = hn;
            }
        }
        __syncthreads();

        // ---- Phase III: single rendezvous; restage both h buffers ----
        if (tid == 0) arrive_release(&g_cnt0);
        if (j < SEQ) {
            if (lane == 4) {
                const unsigned tgt = (unsigned)(NCTA * (j + 1));
                while (ld_acquire_u(&g_cnt0) < tgt) { }
            }
            __syncwarp();
            // combined stage with full MLP: 16 LDGs in flight, then 16 STS
            float4 a[8], b8[8];
            const float* h0src = g_h0[wb2];
            const float* h1src = g_h1[wb2];
#pragma unroll
            for (int i = 0; i < 8; i++)
                a[i] = __ldcg((const float4*)(h0src + (brow * 8 + i) * HID + cidx * 4));
#pragma unroll
            for (int i = 0; i < 8; i++)
                b8[i] = __ldcg((const float4*)(h1src + (brow * 8 + i) * HID + cidx * 4));
            float* d0 = hs0 + cidx * HSTR2;
            float* d1 = hs1 + cidx * HSTR2;
#pragma unroll
            for (int i = 0; i < 8; i++) {
                *(float4*)(d0 + (brow * 8 + i) * 4) = a[i];
                *(float4*)(d1 + (brow * 8 + i) * 4) = b8[i];
            }
        }
        __syncthreads();
    }
}

// ---------------- launch ----------------
extern "C" void kernel_launch(void* const* d_in, const int* in_sizes, int n_in,
                              void* d_out, int out_size) {
    const int*   src  = (const int*)  d_in[0];
    const float* emb  = (const float*)d_in[2];
    const float* Wk   = (const float*)d_in[3];
    const float* Wr   = (const float*)d_in[4];
    const float* bias = (const float*)d_in[5];
    float* out = (float*)d_out;
    float* out_emb = out + (size_t)BATCH * SEQ * HID;

    init_kernel<<<64, 256>>>();
    embed_kernel<<<BATCH * SEQ, 128>>>(src, emb, out_emb);
    wstage_kernel<<<NCTA, 256>>>(Wk, Wr);
    gemm_zx0<<<dim3(G4 / 128, (BATCH * SEQ) / 128), 256>>>(out_emb, Wk, bias);

    cudaFuncSetAttribute(persist_kernel, cudaFuncAttributeMaxDynamicSharedMemorySize, SMEM_FL * 4);
    persist_kernel<<<NCTA, TPB, SMEM_FL * 4>>>(Wk, Wr, bias, out);
}